// round 1
// baseline (speedup 1.0000x reference)
#include <cuda_runtime.h>
#include <math.h>
#include <stdint.h>

// Problem dims
#define B_   64
#define T_   2048
#define IN_  512
#define H_   128
#define G3   384            // 3*H
#define EPS_ 1e-5f

// ---------------- device scratch (no runtime allocation allowed) ----------------
// xp: input projections, layout [dir][B][T][3H]. Layer-1 reuses region 0.
__device__ float g_xp[(size_t)2 * B_ * T_ * G3];      // ~402 MB
// x1: concat(of, ob), layout [B][T][2H]
__device__ float g_x1[(size_t)B_ * T_ * 2 * H_];      // ~134 MB
// final hidden state of layer-1 backward
__device__ float g_hN[B_ * H_];

// ---------------- packed fp32x2 FMA (double-rate fp32 on sm_103a) ----------------
__device__ __forceinline__ unsigned long long ffma2(unsigned long long a,
                                                    unsigned long long b,
                                                    unsigned long long c) {
    unsigned long long d;
    asm("fma.rn.f32x2 %0, %1, %2, %3;" : "=l"(d) : "l"(a), "l"(b), "l"(c));
    return d;
}
__device__ __forceinline__ float2 u2f(unsigned long long u) {
    float2 f;
    asm("mov.b64 {%0, %1}, %2;" : "=f"(f.x), "=f"(f.y) : "l"(u));
    return f;
}

// =======================================================================
// Projection GEMM:  C[m][n] = sum_k A[m][k] * W[n][k] + bias[n]
// A: [M=131072, K] row-major.  W: [384, K] row-major.  C -> g_xp region z.
// 128x128x16 tile, 256 threads, 8x8 micro-tile, all-FFMA2 inner loop.
// =======================================================================
#define BM 128
#define BN 128
#define BK 16

__global__ __launch_bounds__(256, 2)
void proj_gemm(const float* __restrict__ A,          // null -> use g_x1
               int K,
               const float* __restrict__ W0, const float* __restrict__ bias0,
               const float* __restrict__ W1, const float* __restrict__ bias1)
{
    const float* Ap   = A ? A : g_x1;
    const float* W    = blockIdx.z ? W1 : W0;
    const float* bias = blockIdx.z ? bias1 : bias0;
    float* C = g_xp + (size_t)blockIdx.z * B_ * T_ * G3;

    __shared__ float2 Ad[BK][BM];   // duplicated (a,a) pairs, 16 KB
    __shared__ float  Bs[BK][BN];   // 8 KB

    const int tid = threadIdx.x;
    const int tx  = tid & 15;       // n-group
    const int ty  = tid >> 4;       // m-group
    const size_t rowA0 = (size_t)blockIdx.x * BM;
    const int    coln0 = blockIdx.y * BN;

    unsigned long long acc[8][4];
#pragma unroll
    for (int i = 0; i < 8; i++)
#pragma unroll
        for (int j = 0; j < 4; j++) acc[i][j] = 0ull;

    const int nkt = K / BK;
    for (int kt = 0; kt < nkt; kt++) {
        __syncthreads();
#pragma unroll
        for (int p = 0; p < 2; p++) {
            int f   = p * 256 + tid;     // float4 index 0..511
            int row = f >> 2;            // 0..127
            int kq  = (f & 3) * 4;
            float4 av = *(const float4*)(Ap + (rowA0 + row) * K + (size_t)kt * BK + kq);
            Ad[kq + 0][row] = make_float2(av.x, av.x);
            Ad[kq + 1][row] = make_float2(av.y, av.y);
            Ad[kq + 2][row] = make_float2(av.z, av.z);
            Ad[kq + 3][row] = make_float2(av.w, av.w);
            float4 wv = *(const float4*)(W + (size_t)(coln0 + row) * K + (size_t)kt * BK + kq);
            Bs[kq + 0][row] = wv.x;
            Bs[kq + 1][row] = wv.y;
            Bs[kq + 2][row] = wv.z;
            Bs[kq + 3][row] = wv.w;
        }
        __syncthreads();
#pragma unroll
        for (int kk = 0; kk < BK; kk++) {
            const ulonglong2* apv = (const ulonglong2*)&Ad[kk][ty * 8];
            ulonglong2 a0 = apv[0], a1 = apv[1], a2 = apv[2], a3 = apv[3];
            unsigned long long aq[8] = {a0.x, a0.y, a1.x, a1.y, a2.x, a2.y, a3.x, a3.y};
            const ulonglong2* bpv = (const ulonglong2*)&Bs[kk][tx * 8];
            ulonglong2 b0 = bpv[0], b1 = bpv[1];
            unsigned long long bq[4] = {b0.x, b0.y, b1.x, b1.y};
#pragma unroll
            for (int i = 0; i < 8; i++)
#pragma unroll
                for (int j = 0; j < 4; j++)
                    acc[i][j] = ffma2(aq[i], bq[j], acc[i][j]);
        }
    }

    // epilogue
    const int nb = coln0 + tx * 8;
    float bias8[8];
#pragma unroll
    for (int j = 0; j < 8; j++) bias8[j] = bias[nb + j];
#pragma unroll
    for (int i = 0; i < 8; i++) {
        size_t m = rowA0 + ty * 8 + i;
        float2 p0 = u2f(acc[i][0]), p1 = u2f(acc[i][1]);
        float2 p2 = u2f(acc[i][2]), p3 = u2f(acc[i][3]);
        float4 o0 = make_float4(p0.x + bias8[0], p0.y + bias8[1],
                                p1.x + bias8[2], p1.y + bias8[3]);
        float4 o1 = make_float4(p2.x + bias8[4], p2.y + bias8[5],
                                p3.x + bias8[6], p3.y + bias8[7]);
        *(float4*)(C + m * G3 + nb)     = o0;
        *(float4*)(C + m * G3 + nb + 4) = o1;
    }
}

// =======================================================================
// GRU sequential scan. One block per (direction, batch). 384 threads,
// one per gate output. Whh row in registers, h broadcast from shared.
// =======================================================================
__global__ __launch_bounds__(384, 1)
void gru_scan(const float* __restrict__ WhhF, const float* __restrict__ bhhF,
              const float* __restrict__ WhhB, const float* __restrict__ bhhB,
              int write_x1, int write_hN, int ndir)
{
    int bid = blockIdx.x;
    int dir, b;
    if (ndir == 2) { dir = bid >> 6; b = bid & 63; }
    else           { dir = 1;        b = bid; }      // layer-1: backward only

    const float* Whh = dir ? WhhB : WhhF;
    const float* bhh = dir ? bhhB : bhhF;
    // layer-1 xp lives in region 0
    const float* xp = g_xp + ((size_t)((ndir == 2) ? dir : 0) * B_ + b) * (size_t)T_ * G3;

    const int j = threadIdx.x;

    __shared__ float sh_h[H_];
    __shared__ float sh_g[G3];
    __shared__ float sh_xn[H_];

    // Whh row j -> registers as packed fp32 pairs (row is 8B-aligned: 128 floats)
    unsigned long long w[H_ / 2];
    {
        const unsigned long long* wr =
            (const unsigned long long*)(Whh + (size_t)j * H_);
#pragma unroll
        for (int k = 0; k < H_ / 2; k++) w[k] = wr[k];
    }
    const float bj = bhh[j];
    if (j < H_) sh_h[j] = 0.f;
    __syncthreads();

    const int t0 = dir ? (T_ - 1) : 0;
    const int dt = dir ? -1 : 1;
    const unsigned long long* h2 = (const unsigned long long*)sh_h;

    float xv = xp[(size_t)t0 * G3 + j];           // prefetch step 0

    for (int s = 0; s < T_; s++) {
        const int t = t0 + s * dt;
        // prefetch next step's xp early; its latency hides under the dot product
        float xv_next = 0.f;
        if (s + 1 < T_) xv_next = xp[(size_t)(t + dt) * G3 + j];

        unsigned long long acc0 = 0ull, acc1 = 0ull;
#pragma unroll
        for (int k = 0; k < H_ / 2; k += 2) {
            acc0 = ffma2(h2[k],     w[k],     acc0);
            acc1 = ffma2(h2[k + 1], w[k + 1], acc1);
        }
        float2 a0 = u2f(acc0), a1 = u2f(acc1);
        float g = a0.x + a0.y + a1.x + a1.y + bj;

        if (j < 2 * H_) { sh_g[j] = g + xv; }          // r, z gates: sum both parts
        else            { sh_g[j] = g; sh_xn[j - 2 * H_] = xv; }  // n: keep split
        __syncthreads();

        if (j < H_) {
            float r  = 1.0f / (1.0f + expf(-sh_g[j]));
            float z  = 1.0f / (1.0f + expf(-sh_g[H_ + j]));
            float n  = tanhf(sh_xn[j] + r * sh_g[2 * H_ + j]);
            float hn = (1.0f - z) * n + z * sh_h[j];
            sh_h[j] = hn;
            if (write_x1)
                g_x1[((size_t)b * T_ + t) * (2 * H_) + (size_t)dir * H_ + j] = hn;
        }
        __syncthreads();
        xv = xv_next;
    }

    if (write_hN && j < H_) g_hN[b * H_ + j] = sh_h[j];
}

// =======================================================================
// Decoder: mish -> LN -> Linear(H,H) -> mish -> LN -> Linear(H,1)
// One block per batch row, 128 threads.
// =======================================================================
__device__ __forceinline__ float mishf(float x) {
    float sp = (x > 20.f) ? x : log1pf(expf(x));
    return x * tanhf(sp);
}

__device__ __forceinline__ float blockReduceSum(float v) {
#pragma unroll
    for (int o = 16; o > 0; o >>= 1) v += __shfl_xor_sync(0xffffffffu, v, o);
    __shared__ float s[4];
    int w = threadIdx.x >> 5;
    if ((threadIdx.x & 31) == 0) s[w] = v;
    __syncthreads();
    v = s[0] + s[1] + s[2] + s[3];
    __syncthreads();
    return v;
}

__global__ __launch_bounds__(128, 1)
void decoder(const float* __restrict__ g1, const float* __restrict__ be1,
             const float* __restrict__ W1, const float* __restrict__ b1,
             const float* __restrict__ g2, const float* __restrict__ be2,
             const float* __restrict__ W2, const float* __restrict__ b2,
             float* __restrict__ out)
{
    const int b = blockIdx.x, j = threadIdx.x;
    __shared__ float sv[H_];

    // post_gru: mish -> LN
    float v = mishf(g_hN[b * H_ + j]);
    float m = blockReduceSum(v) * (1.0f / H_);
    float d = v - m;
    float var = blockReduceSum(d * d) * (1.0f / H_);
    float y = d * rsqrtf(var + EPS_) * g1[j] + be1[j];
    sv[j] = y;
    __syncthreads();

    // Linear(H,H) + mish
    float t = b1[j];
#pragma unroll 4
    for (int k = 0; k < H_; k++) t = fmaf(sv[k], W1[j * H_ + k], t);
    float u = mishf(t);
    __syncthreads();

    // LN
    m = blockReduceSum(u) * (1.0f / H_);
    d = u - m;
    var = blockReduceSum(d * d) * (1.0f / H_);
    float zz = d * rsqrtf(var + EPS_) * g2[j] + be2[j];

    // Linear(H,1)
    float p = blockReduceSum(zz * W2[j]);
    if (j == 0) out[b] = p + b2[0];
}

// =======================================================================
// Host launcher
// =======================================================================
extern "C" void kernel_launch(void* const* d_in, const int* in_sizes, int n_in,
                              void* d_out, int out_size)
{
    (void)in_sizes; (void)n_in; (void)out_size;
    const float* x     = (const float*)d_in[0];
    const float* Wih0f = (const float*)d_in[1];
    const float* Whh0f = (const float*)d_in[2];
    const float* bih0f = (const float*)d_in[3];
    const float* bhh0f = (const float*)d_in[4];
    const float* Wih0b = (const float*)d_in[5];
    const float* Whh0b = (const float*)d_in[6];
    const float* bih0b = (const float*)d_in[7];
    const float* bhh0b = (const float*)d_in[8];
    // d_in[9..12] = layer-1 forward params: provably unused by the reference output
    const float* Wih1b = (const float*)d_in[13];
    const float* Whh1b = (const float*)d_in[14];
    const float* bih1b = (const float*)d_in[15];
    const float* bhh1b = (const float*)d_in[16];
    const float* g1  = (const float*)d_in[17];
    const float* be1 = (const float*)d_in[18];
    const float* W1  = (const float*)d_in[19];
    const float* b1  = (const float*)d_in[20];
    const float* g2  = (const float*)d_in[21];
    const float* be2 = (const float*)d_in[22];
    const float* W2  = (const float*)d_in[23];
    const float* b2  = (const float*)d_in[24];

    // Layer 0 input projections (both directions in one launch, z = dir)
    {
        dim3 grid((B_ * T_) / BM, G3 / BN, 2);
        proj_gemm<<<grid, 256>>>(x, IN_, Wih0f, bih0f, Wih0b, bih0b);
    }
    // Layer 0 scans: 128 blocks = 2 dirs x 64 batches, writes g_x1
    gru_scan<<<128, 384>>>(Whh0f, bhh0f, Whh0b, bhh0b, /*write_x1=*/1, /*write_hN=*/0, /*ndir=*/2);
    // Layer 1 backward input projection (reuses g_xp region 0)
    {
        dim3 grid((B_ * T_) / BM, G3 / BN, 1);
        proj_gemm<<<grid, 256>>>(nullptr, 2 * H_, Wih1b, bih1b, Wih1b, bih1b);
    }
    // Layer 1 backward scan: keep only final hidden state
    gru_scan<<<64, 384>>>(Whh1b, bhh1b, Whh1b, bhh1b, /*write_x1=*/0, /*write_hN=*/1, /*ndir=*/1);
    // Decoder
    decoder<<<64, 128>>>(g1, be1, W1, b1, g2, be2, W2, b2, (float*)d_out);
}

// round 2
// speedup vs baseline: 1.1203x; 1.1203x over previous
#include <cuda_runtime.h>
#include <math.h>
#include <stdint.h>

// Problem dims
#define B_   64
#define T_   2048
#define IN_  512
#define H_   128
#define G3   384            // 3*H
#define EPS_ 1e-5f

// ---------------- device scratch (no runtime allocation allowed) ----------------
__device__ float g_xp[(size_t)2 * B_ * T_ * G3];      // [dir][B][T][3H]
__device__ float g_x1[(size_t)B_ * T_ * 2 * H_];      // [B][T][2H]
__device__ float g_hN[B_ * H_];

// ---------------- packed fp32x2 FMA (double-rate fp32 on sm_103a) ----------------
__device__ __forceinline__ unsigned long long ffma2(unsigned long long a,
                                                    unsigned long long b,
                                                    unsigned long long c) {
    unsigned long long d;
    asm("fma.rn.f32x2 %0, %1, %2, %3;" : "=l"(d) : "l"(a), "l"(b), "l"(c));
    return d;
}
__device__ __forceinline__ float2 u2f(unsigned long long u) {
    float2 f;
    asm("mov.b64 {%0, %1}, %2;" : "=f"(f.x), "=f"(f.y) : "l"(u));
    return f;
}
__device__ __forceinline__ float tanh_fast(float x) {
    float y;
    asm("tanh.approx.f32 %0, %1;" : "=f"(y) : "f"(x));
    return y;
}
__device__ __forceinline__ float sigmoid_fast(float x) {
    // sigmoid(x) = 0.5*tanh(x/2) + 0.5  (single MUFU-class op)
    return fmaf(0.5f, tanh_fast(0.5f * x), 0.5f);
}

// =======================================================================
// Projection GEMM:  C[m][n] = sum_k A[m][k] * W[n][k] + bias[n]
// 128x128x16 tile, 256 threads, 8x8 micro-tile, all-FFMA2 inner loop.
// Double-buffered shared memory: ONE __syncthreads per k-tile, global
// loads for tile t+1 staged in registers while computing tile t.
// =======================================================================
#define BM 128
#define BN 128
#define BK 16

__global__ __launch_bounds__(256, 2)
void proj_gemm(const float* __restrict__ A,          // null -> use g_x1
               int K,
               const float* __restrict__ W0, const float* __restrict__ bias0,
               const float* __restrict__ W1, const float* __restrict__ bias1)
{
    const float* Ap   = A ? A : g_x1;
    const float* W    = blockIdx.z ? W1 : W0;
    const float* bias = blockIdx.z ? bias1 : bias0;
    float* C = g_xp + (size_t)blockIdx.z * B_ * T_ * G3;

    // double buffers: 2*(16KB + 8KB) = 49152 bytes = exactly 48KB static limit
    __shared__ float2 Ad[2][BK][BM];
    __shared__ float  Bs[2][BK][BN];

    const int tid = threadIdx.x;
    const int tx  = tid & 15;       // n-group
    const int ty  = tid >> 4;       // m-group
    const size_t rowA0 = (size_t)blockIdx.x * BM;
    const int    coln0 = blockIdx.y * BN;

    // per-thread load coordinates (2 float4 of A, 2 float4 of W per tile)
    int lrow[2], lkq[2];
#pragma unroll
    for (int p = 0; p < 2; p++) {
        int f = p * 256 + tid;
        lrow[p] = f >> 2;
        lkq[p]  = (f & 3) * 4;
    }

    unsigned long long acc[8][4];
#pragma unroll
    for (int i = 0; i < 8; i++)
#pragma unroll
        for (int j = 0; j < 4; j++) acc[i][j] = 0ull;

    const int nkt = K / BK;

    float4 av[2], wv[2];
    // prologue: load tile 0
#pragma unroll
    for (int p = 0; p < 2; p++) {
        av[p] = *(const float4*)(Ap + (rowA0 + lrow[p]) * K + lkq[p]);
        wv[p] = *(const float4*)(W + (size_t)(coln0 + lrow[p]) * K + lkq[p]);
    }
#pragma unroll
    for (int p = 0; p < 2; p++) {
        int row = lrow[p], kq = lkq[p];
        Ad[0][kq + 0][row] = make_float2(av[p].x, av[p].x);
        Ad[0][kq + 1][row] = make_float2(av[p].y, av[p].y);
        Ad[0][kq + 2][row] = make_float2(av[p].z, av[p].z);
        Ad[0][kq + 3][row] = make_float2(av[p].w, av[p].w);
        Bs[0][kq + 0][row] = wv[p].x;
        Bs[0][kq + 1][row] = wv[p].y;
        Bs[0][kq + 2][row] = wv[p].z;
        Bs[0][kq + 3][row] = wv[p].w;
    }
    __syncthreads();

    for (int kt = 0; kt < nkt; kt++) {
        const int cur = kt & 1;
        const bool more = (kt + 1 < nkt);
        // stage next tile's global loads (latency hides under compute)
        if (more) {
            const size_t ko = (size_t)(kt + 1) * BK;
#pragma unroll
            for (int p = 0; p < 2; p++) {
                av[p] = *(const float4*)(Ap + (rowA0 + lrow[p]) * K + ko + lkq[p]);
                wv[p] = *(const float4*)(W + (size_t)(coln0 + lrow[p]) * K + ko + lkq[p]);
            }
        }
        // compute on current buffer
#pragma unroll
        for (int kk = 0; kk < BK; kk++) {
            const ulonglong2* apv = (const ulonglong2*)&Ad[cur][kk][ty * 8];
            ulonglong2 a0 = apv[0], a1 = apv[1], a2 = apv[2], a3 = apv[3];
            unsigned long long aq[8] = {a0.x, a0.y, a1.x, a1.y, a2.x, a2.y, a3.x, a3.y};
            const ulonglong2* bpv = (const ulonglong2*)&Bs[cur][kk][tx * 8];
            ulonglong2 b0 = bpv[0], b1 = bpv[1];
            unsigned long long bq[4] = {b0.x, b0.y, b1.x, b1.y};
#pragma unroll
            for (int i = 0; i < 8; i++)
#pragma unroll
                for (int j = 0; j < 4; j++)
                    acc[i][j] = ffma2(aq[i], bq[j], acc[i][j]);
        }
        // store staged tile into the other buffer (safe: its readers synced
        // at the end of iteration kt-1)
        if (more) {
            const int nxt = cur ^ 1;
#pragma unroll
            for (int p = 0; p < 2; p++) {
                int row = lrow[p], kq = lkq[p];
                Ad[nxt][kq + 0][row] = make_float2(av[p].x, av[p].x);
                Ad[nxt][kq + 1][row] = make_float2(av[p].y, av[p].y);
                Ad[nxt][kq + 2][row] = make_float2(av[p].z, av[p].z);
                Ad[nxt][kq + 3][row] = make_float2(av[p].w, av[p].w);
                Bs[nxt][kq + 0][row] = wv[p].x;
                Bs[nxt][kq + 1][row] = wv[p].y;
                Bs[nxt][kq + 2][row] = wv[p].z;
                Bs[nxt][kq + 3][row] = wv[p].w;
            }
        }
        __syncthreads();
    }

    // epilogue
    const int nb = coln0 + tx * 8;
    float bias8[8];
#pragma unroll
    for (int j = 0; j < 8; j++) bias8[j] = bias[nb + j];
#pragma unroll
    for (int i = 0; i < 8; i++) {
        size_t m = rowA0 + ty * 8 + i;
        float2 p0 = u2f(acc[i][0]), p1 = u2f(acc[i][1]);
        float2 p2 = u2f(acc[i][2]), p3 = u2f(acc[i][3]);
        float4 o0 = make_float4(p0.x + bias8[0], p0.y + bias8[1],
                                p1.x + bias8[2], p1.y + bias8[3]);
        float4 o1 = make_float4(p2.x + bias8[4], p2.y + bias8[5],
                                p3.x + bias8[6], p3.y + bias8[7]);
        *(float4*)(C + m * G3 + nb)     = o0;
        *(float4*)(C + m * G3 + nb + 4) = o1;
    }
}

// =======================================================================
// GRU sequential scan. One block per (direction, batch). 384 threads,
// one per gate output. Whh row in registers, h broadcast from shared
// via LDS.128; gate nonlinearities via tanh.approx.
// =======================================================================
__global__ __launch_bounds__(384, 1)
void gru_scan(const float* __restrict__ WhhF, const float* __restrict__ bhhF,
              const float* __restrict__ WhhB, const float* __restrict__ bhhB,
              int write_x1, int write_hN, int ndir)
{
    int bid = blockIdx.x;
    int dir, b;
    if (ndir == 2) { dir = bid >> 6; b = bid & 63; }
    else           { dir = 1;        b = bid; }      // layer-1: backward only

    const float* Whh = dir ? WhhB : WhhF;
    const float* bhh = dir ? bhhB : bhhF;
    const float* xp = g_xp + ((size_t)((ndir == 2) ? dir : 0) * B_ + b) * (size_t)T_ * G3;

    const int j = threadIdx.x;

    __shared__ __align__(16) float sh_h[H_];
    __shared__ float sh_g[G3];
    __shared__ float sh_xn[H_];

    // Whh row j -> registers as packed fp32 pairs
    unsigned long long w[H_ / 2];
    {
        const unsigned long long* wr =
            (const unsigned long long*)(Whh + (size_t)j * H_);
#pragma unroll
        for (int k = 0; k < H_ / 2; k++) w[k] = wr[k];
    }
    const float bj = bhh[j];
    if (j < H_) sh_h[j] = 0.f;
    __syncthreads();

    const int t0 = dir ? (T_ - 1) : 0;
    const int dt = dir ? -1 : 1;
    const ulonglong2* h4 = (const ulonglong2*)sh_h;

    float xv = xp[(size_t)t0 * G3 + j];           // prefetch step 0

    for (int s = 0; s < T_; s++) {
        const int t = t0 + s * dt;
        float xv_next = 0.f;
        if (s + 1 < T_) xv_next = xp[(size_t)(t + dt) * G3 + j];

        unsigned long long acc0 = 0ull, acc1 = 0ull;
#pragma unroll
        for (int k = 0; k < H_ / 4; k++) {
            ulonglong2 hv = h4[k];                  // LDS.128 broadcast
            acc0 = ffma2(hv.x, w[2 * k],     acc0);
            acc1 = ffma2(hv.y, w[2 * k + 1], acc1);
        }
        float2 a0 = u2f(acc0), a1 = u2f(acc1);
        float g = a0.x + a0.y + a1.x + a1.y + bj;

        if (j < 2 * H_) { sh_g[j] = g + xv; }
        else            { sh_g[j] = g; sh_xn[j - 2 * H_] = xv; }
        __syncthreads();

        if (j < H_) {
            float r  = sigmoid_fast(sh_g[j]);
            float z  = sigmoid_fast(sh_g[H_ + j]);
            float n  = tanh_fast(sh_xn[j] + r * sh_g[2 * H_ + j]);
            float hn = (1.0f - z) * n + z * sh_h[j];
            sh_h[j] = hn;
            if (write_x1)
                g_x1[((size_t)b * T_ + t) * (2 * H_) + (size_t)dir * H_ + j] = hn;
        }
        __syncthreads();
        xv = xv_next;
    }

    if (write_hN && j < H_) g_hN[b * H_ + j] = sh_h[j];
}

// =======================================================================
// Decoder: mish -> LN -> Linear(H,H) -> mish -> LN -> Linear(H,1)
// =======================================================================
__device__ __forceinline__ float mishf(float x) {
    float sp = (x > 20.f) ? x : log1pf(expf(x));
    return x * tanhf(sp);
}

__device__ __forceinline__ float blockReduceSum(float v) {
#pragma unroll
    for (int o = 16; o > 0; o >>= 1) v += __shfl_xor_sync(0xffffffffu, v, o);
    __shared__ float s[4];
    int w = threadIdx.x >> 5;
    if ((threadIdx.x & 31) == 0) s[w] = v;
    __syncthreads();
    v = s[0] + s[1] + s[2] + s[3];
    __syncthreads();
    return v;
}

__global__ __launch_bounds__(128, 1)
void decoder(const float* __restrict__ g1, const float* __restrict__ be1,
             const float* __restrict__ W1, const float* __restrict__ b1,
             const float* __restrict__ g2, const float* __restrict__ be2,
             const float* __restrict__ W2, const float* __restrict__ b2,
             float* __restrict__ out)
{
    const int b = blockIdx.x, j = threadIdx.x;
    __shared__ float sv[H_];

    float v = mishf(g_hN[b * H_ + j]);
    float m = blockReduceSum(v) * (1.0f / H_);
    float d = v - m;
    float var = blockReduceSum(d * d) * (1.0f / H_);
    float y = d * rsqrtf(var + EPS_) * g1[j] + be1[j];
    sv[j] = y;
    __syncthreads();

    float t = b1[j];
#pragma unroll 4
    for (int k = 0; k < H_; k++) t = fmaf(sv[k], W1[j * H_ + k], t);
    float u = mishf(t);
    __syncthreads();

    m = blockReduceSum(u) * (1.0f / H_);
    d = u - m;
    var = blockReduceSum(d * d) * (1.0f / H_);
    float zz = d * rsqrtf(var + EPS_) * g2[j] + be2[j];

    float p = blockReduceSum(zz * W2[j]);
    if (j == 0) out[b] = p + b2[0];
}

// =======================================================================
// Host launcher
// =======================================================================
extern "C" void kernel_launch(void* const* d_in, const int* in_sizes, int n_in,
                              void* d_out, int out_size)
{
    (void)in_sizes; (void)n_in; (void)out_size;
    const float* x     = (const float*)d_in[0];
    const float* Wih0f = (const float*)d_in[1];
    const float* Whh0f = (const float*)d_in[2];
    const float* bih0f = (const float*)d_in[3];
    const float* bhh0f = (const float*)d_in[4];
    const float* Wih0b = (const float*)d_in[5];
    const float* Whh0b = (const float*)d_in[6];
    const float* bih0b = (const float*)d_in[7];
    const float* bhh0b = (const float*)d_in[8];
    // d_in[9..12] = layer-1 forward params: unused by the reference output
    const float* Wih1b = (const float*)d_in[13];
    const float* Whh1b = (const float*)d_in[14];
    const float* bih1b = (const float*)d_in[15];
    const float* bhh1b = (const float*)d_in[16];
    const float* g1  = (const float*)d_in[17];
    const float* be1 = (const float*)d_in[18];
    const float* W1  = (const float*)d_in[19];
    const float* b1  = (const float*)d_in[20];
    const float* g2  = (const float*)d_in[21];
    const float* be2 = (const float*)d_in[22];
    const float* W2  = (const float*)d_in[23];
    const float* b2  = (const float*)d_in[24];

    {
        dim3 grid((B_ * T_) / BM, G3 / BN, 2);
        proj_gemm<<<grid, 256>>>(x, IN_, Wih0f, bih0f, Wih0b, bih0b);
    }
    gru_scan<<<128, 384>>>(Whh0f, bhh0f, Whh0b, bhh0b, 1, 0, 2);
    {
        dim3 grid((B_ * T_) / BM, G3 / BN, 1);
        proj_gemm<<<grid, 256>>>(nullptr, 2 * H_, Wih1b, bih1b, Wih1b, bih1b);
    }
    gru_scan<<<64, 384>>>(Whh1b, bhh1b, Whh1b, bhh1b, 0, 1, 1);
    decoder<<<64, 128>>>(g1, be1, W1, b1, g2, be2, W2, b2, (float*)d_out);
}